// round 15
// baseline (speedup 1.0000x reference)
#include <cuda_runtime.h>
#include <cuda_bf16.h>

#define B 2
#define N 8192
#define M 8192
#define D 64
#define KNN 16
#define QTOT (B * M)

#define NCHUNK 8
#define CHUNK (N / NCHUNK)     // 1024
#define CAP 32                 // per-thread append-stack capacity (pow2)
#define SENT 3.4e38f
#define EPSF 5e-5f             // t-space filter margin

// Scratch (allocation-free: __device__ globals)
__device__ float g_f[B * N * D];                    // projected features, 4MB
__device__ int   g_idx[B * M * KNN];                // final knn indices
__device__ float g_pd[B * M * NCHUNK * KNN];        // partial top-16 dists
__device__ int   g_pi[B * M * NCHUNK * KNN];        // partial top-16 ids
__device__ int   g_ovf[B * M * NCHUNK];             // overflow flags

__device__ __forceinline__ unsigned long long fma2(
    unsigned long long a, unsigned long long b, unsigned long long c) {
    unsigned long long r;
    asm("fma.rn.f32x2 %0, %1, %2, %3;" : "=l"(r) : "l"(a), "l"(b), "l"(c));
    return r;
}
__device__ __forceinline__ unsigned long long mul2(
    unsigned long long a, unsigned long long b) {
    unsigned long long r;
    asm("mul.rn.f32x2 %0, %1, %2;" : "=l"(r) : "l"(a), "l"(b));
    return r;
}
__device__ __forceinline__ unsigned long long add2(
    unsigned long long a, unsigned long long b) {
    unsigned long long r;
    asm("add.rn.f32x2 %0, %1, %2;" : "=l"(r) : "l"(a), "l"(b));
    return r;
}
__device__ __forceinline__ unsigned long long pack2(float lo, float hi) {
    unsigned long long r;
    asm("mov.b64 %0, {%1, %2};" : "=l"(r) : "f"(lo), "f"(hi));
    return r;
}
__device__ __forceinline__ void unpack2(unsigned long long v, float& lo, float& hi) {
    asm("mov.b64 {%0, %1}, %2;" : "=f"(lo), "=f"(hi) : "l"(v));
}

// Per-query radius^2 threshold covering ~TARGET points in expectation.
// Performance hint only: merge kernel verifies completeness and falls back.
__device__ __forceinline__ float query_thresh(float qx, float qy, float qz) {
    const float TARGET = 48.0f;
    const float KVOL = (float)N * 4.18879f;   // N * (4/3)pi
    float r = cbrtf(TARGET / KVOL);
#pragma unroll
    for (int it = 0; it < 3; it++) {
        float inv2r = 0.5f / r;
        float fx = (fminf(qx, r) + fminf(1.0f - qx, r)) * inv2r;
        float fy = (fminf(qy, r) + fminf(1.0f - qy, r)) * inv2r;
        float fz = (fminf(qz, r) + fminf(1.0f - qz, r)) * inv2r;
        float c = fmaxf(fx * fy * fz, 0.125f);
        r = cbrtf(TARGET / (KVOL * c));
    }
    return r * r;
}

// ---------------------------------------------------------------------------
// Kernel 1: f = feature1 @ Wp + bp (16 rows/block)
// ---------------------------------------------------------------------------
__global__ __launch_bounds__(256) void proj_kernel(
    const float* __restrict__ feat, const float* __restrict__ Wp,
    const float* __restrict__ bp)
{
    __shared__ float Ws[64 * 64];
    __shared__ float Fs[16][64];
    for (int i = threadIdx.x; i < 64 * 64; i += 256) Ws[i] = Wp[i];
    int r0 = blockIdx.x * 16;
    for (int i = threadIdx.x; i < 16 * 64; i += 256)
        Fs[i >> 6][i & 63] = feat[(r0 + (i >> 6)) * 64 + (i & 63)];
    __syncthreads();
    int rr = threadIdx.x >> 6;
    int c  = threadIdx.x & 63;
    float a0 = bp[c], a1 = a0, a2 = a0, a3 = a0;
#pragma unroll
    for (int d = 0; d < 64; d++) {
        float w = Ws[d * 64 + c];
        a0 = fmaf(Fs[rr     ][d], w, a0);
        a1 = fmaf(Fs[rr +  4][d], w, a1);
        a2 = fmaf(Fs[rr +  8][d], w, a2);
        a3 = fmaf(Fs[rr + 12][d], w, a3);
    }
    g_f[(r0 + rr     ) * 64 + c] = a0;
    g_f[(r0 + rr +  4) * 64 + c] = a1;
    g_f[(r0 + rr +  8) * 64 + c] = a2;
    g_f[(r0 + rr + 12) * 64 + c] = a3;
}

// ---------------------------------------------------------------------------
// Kernel 2a: packed-pair filtered scan. Tile stored as pair-SoA (x/y/z/w as
// f32x2 pairs); 4 candidates per step via mul/fma/add.rn.f32x2. Pass test =
// sign bit of packed (t - rhs): rn is sign-exact and fma2(w,-0.5,-u) is the
// exact negation of fmaf(0.5,w,u), so computed-pass is a superset of the
// margined test {t > rhs} which (EPSF) is a superset of {d < T}. False
// positives are harmless (replay ranks them); false negatives impossible, so
// the merge's sentinel/overflow fallback remains an airtight exactness guard.
// Replay recomputes d with the textually original formula -> selection
// semantics identical. grid = (M/128, NCHUNK, B), block = 128
// ---------------------------------------------------------------------------
__global__ __launch_bounds__(128) void knn_part_kernel(
    const float* __restrict__ xyz1, const float* __restrict__ xyz2)
{
    __shared__ ulonglong2 PX[CHUNK / 4], PY[CHUNK / 4], PZ[CHUNK / 4], PW[CHUNK / 4]; // 16KB
    __shared__ int stk[128][CAP];        // 16KB index stacks
    int b     = blockIdx.z;
    int chunk = blockIdx.y;
    int m     = blockIdx.x * 128 + threadIdx.x;
    const float* x2 = xyz2 + ((size_t)b * M + m) * 3;
    float qx = x2[0], qy = x2[1], qz = x2[2];
    float qs = qx * qx + qy * qy + qz * qz;
    float T  = query_thresh(qx, qy, qz);
    float u  = 0.5f * (qs - T) - EPSF;      // folded margin

    int nbeg = chunk * CHUNK;
    const float* base = xyz1 + ((size_t)b * N + nbeg) * 3;
    {
        int c0 = threadIdx.x * 8;            // 8 consecutive candidates/thread
        float xx[8], yy[8], zz[8];
#pragma unroll
        for (int i = 0; i < 8; i++) {
            xx[i] = base[(c0 + i) * 3 + 0];
            yy[i] = base[(c0 + i) * 3 + 1];
            zz[i] = base[(c0 + i) * 3 + 2];
        }
#pragma unroll
        for (int g = 0; g < 2; g++) {
            int o = g * 4;
            int gi = threadIdx.x * 2 + g;
            PX[gi] = make_ulonglong2(pack2(xx[o], xx[o + 1]), pack2(xx[o + 2], xx[o + 3]));
            PY[gi] = make_ulonglong2(pack2(yy[o], yy[o + 1]), pack2(yy[o + 2], yy[o + 3]));
            PZ[gi] = make_ulonglong2(pack2(zz[o], zz[o + 1]), pack2(zz[o + 2], zz[o + 3]));
            float w0 = xx[o    ] * xx[o    ] + yy[o    ] * yy[o    ] + zz[o    ] * zz[o    ];
            float w1 = xx[o + 1] * xx[o + 1] + yy[o + 1] * yy[o + 1] + zz[o + 1] * zz[o + 1];
            float w2 = xx[o + 2] * xx[o + 2] + yy[o + 2] * yy[o + 2] + zz[o + 2] * zz[o + 2];
            float w3 = xx[o + 3] * xx[o + 3] + yy[o + 3] * yy[o + 3] + zz[o + 3] * zz[o + 3];
            PW[gi] = make_ulonglong2(pack2(w0, w1), pack2(w2, w3));
        }
    }
    __syncthreads();

    unsigned long long qx2 = pack2(qx, qx), qy2 = pack2(qy, qy), qz2 = pack2(qz, qz);
    unsigned long long mh2 = pack2(-0.5f, -0.5f), mu2 = pack2(-u, -u);
    int* my = stk[threadIdx.x];
    int cnt = 0;
#pragma unroll 4
    for (int g = 0; g < CHUNK / 4; g++) {
        ulonglong2 xv = PX[g], yv = PY[g], zv = PZ[g], wv = PW[g];
        // same fma sequence as original: t = qx*x; t=fma(qy,y,t); t=fma(qz,z,t)
        unsigned long long t0 = fma2(zv.x, qz2, fma2(yv.x, qy2, mul2(xv.x, qx2)));
        unsigned long long t1 = fma2(zv.y, qz2, fma2(yv.y, qy2, mul2(xv.y, qx2)));
        unsigned long long d0 = add2(t0, fma2(wv.x, mh2, mu2));   // t - (0.5w + u)
        unsigned long long d1 = add2(t1, fma2(wv.y, mh2, mu2));
        float f0, f1, f2, f3;
        unpack2(d0, f0, f1); unpack2(d1, f2, f3);
        bool p0 = __float_as_int(f0) >= 0;
        bool p1 = __float_as_int(f1) >= 0;
        bool p2 = __float_as_int(f2) >= 0;
        bool p3 = __float_as_int(f3) >= 0;
        if (p0) my[cnt & (CAP - 1)] = 4 * g + 0;  cnt += p0;
        if (p1) my[cnt & (CAP - 1)] = 4 * g + 1;  cnt += p1;
        if (p2) my[cnt & (CAP - 1)] = 4 * g + 2;  cnt += p2;
        if (p3) my[cnt & (CAP - 1)] = 4 * g + 3;  cnt += p3;
    }

    // replay (ascending-n order): original formula, strict-< sorted insert
    const float* fx = (const float*)PX;   // linear float views of pair-SoA
    const float* fy = (const float*)PY;
    const float* fz = (const float*)PZ;
    const float* fw = (const float*)PW;
    float bd[KNN]; int bi[KNN];
#pragma unroll
    for (int j = 0; j < KNN; j++) { bd[j] = SENT; bi[j] = 0; }
    int kk = cnt < CAP ? cnt : CAP;
    for (int i = 0; i < kk; i++) {
        int jj = my[i];
        float x = fx[jj], y = fy[jj], z = fz[jj], w = fw[jj];
        float t = qx * x;
        t = fmaf(qy, y, t);
        t = fmaf(qz, z, t);
        float d = (qs + w) - 2.0f * t;     // bitwise-same as original kernel
        if (d < bd[KNN - 1]) {
            bd[KNN - 1] = d; bi[KNN - 1] = nbeg + jj;
#pragma unroll
            for (int j = KNN - 1; j > 0; --j) {
                if (bd[j] < bd[j - 1]) {
                    float td = bd[j]; bd[j] = bd[j - 1]; bd[j - 1] = td;
                    int   ti = bi[j]; bi[j] = bi[j - 1]; bi[j - 1] = ti;
                }
            }
        }
    }

    size_t q = (size_t)b * M + m;
    float* pd = g_pd + (q * NCHUNK + chunk) * KNN;
    int*   pi = g_pi + (q * NCHUNK + chunk) * KNN;
#pragma unroll
    for (int j = 0; j < KNN; j++) { pd[j] = bd[j]; pi[j] = bi[j]; }
    g_ovf[q * NCHUNK + chunk] = (cnt > CAP) ? 1 : 0;
}

// ---------------------------------------------------------------------------
// Kernel 2b: exact 8-way merge; fallback to full scan on sentinel/overflow.
// ---------------------------------------------------------------------------
__global__ __launch_bounds__(256) void knn_merge_kernel(
    const float* __restrict__ xyz1, const float* __restrict__ xyz2,
    float* __restrict__ outW)
{
    int q = blockIdx.x * 256 + threadIdx.x;
    if (q >= QTOT) return;
    const float* pd = g_pd + (size_t)q * NCHUNK * KNN;
    const int*   pi = g_pi + (size_t)q * NCHUNK * KNN;

    int ovf = 0;
#pragma unroll
    for (int c = 0; c < NCHUNK; c++) ovf |= g_ovf[(size_t)q * NCHUNK + c];

    int   ptr[NCHUNK];
    float head[NCHUNK];
#pragma unroll
    for (int c = 0; c < NCHUNK; c++) { ptr[c] = 0; head[c] = pd[c * KNN]; }

    int   outi[KNN];
    float first = SENT, last = SENT;
#pragma unroll
    for (int j = 0; j < KNN; j++) {
        int best = 0; float bv = head[0];
#pragma unroll
        for (int c = 1; c < NCHUNK; c++)
            if (head[c] < bv) { bv = head[c]; best = c; }   // earliest chunk wins ties
        outi[j] = pi[best * KNN + ptr[best]];
        if (j == 0) first = bv;
        last = bv;
        ptr[best]++;
        head[best] = (ptr[best] < KNN) ? pd[best * KNN + ptr[best]] : SENT;
    }

    if (ovf || last >= SENT) {
        // fallback: full unfiltered scan (exactness guarantee; ~never taken)
        int b = q >> 13;
        const float* x2 = xyz2 + (size_t)q * 3;
        float qx = x2[0], qy = x2[1], qz = x2[2];
        float qs = qx * qx + qy * qy + qz * qz;
        float bd[KNN];
#pragma unroll
        for (int j = 0; j < KNN; j++) { bd[j] = SENT; outi[j] = 0; }
        const float* base = xyz1 + (size_t)b * N * 3;
        for (int n = 0; n < N; n++) {
            float x = base[n * 3], y = base[n * 3 + 1], z = base[n * 3 + 2];
            float ps = x * x + y * y + z * z;
            float t = qx * x;
            t = fmaf(qy, y, t);
            t = fmaf(qz, z, t);
            float d = (qs + ps) - 2.0f * t;
            if (d < bd[KNN - 1]) {
                bd[KNN - 1] = d; outi[KNN - 1] = n;
#pragma unroll
                for (int j = KNN - 1; j > 0; --j) {
                    if (bd[j] < bd[j - 1]) {
                        float td = bd[j]; bd[j] = bd[j - 1]; bd[j - 1] = td;
                        int   ti = outi[j]; outi[j] = outi[j - 1]; outi[j - 1] = ti;
                    }
                }
            }
        }
        first = bd[0];
    }

#pragma unroll
    for (int j = 0; j < KNN; j++) g_idx[(size_t)q * KNN + j] = outi[j];
    outW[q] = (first > 0.03f) ? 10.0f : 1.0f;
}

// ---------------------------------------------------------------------------
// Kernel 3: gather + MLP + reduction. Identical math to round 14; launch
// bounds tightened to (128,4): forces regs <= 128 (spilling ~20 W2 pairs to
// L1-resident local) to lift occupancy 16% -> 25% and feed the 40%-utilized
// fma pipe.
// ---------------------------------------------------------------------------
#define MLP_BLOCKS 1024         // 4096 warps -> exactly 4 queries each
__global__ __launch_bounds__(128, 4) void mlp_kernel(
    const float* __restrict__ xyz1, const float* __restrict__ xyz2,
    const float* __restrict__ W1, const float* __restrict__ b1,
    const float* __restrict__ W2, const float* __restrict__ b2,
    float* __restrict__ out)
{
    __shared__ float Hs[4][KNN * 64];   // 16KB
    __shared__ float Gs[4][KNN * 64];   // 16KB
    int lane = threadIdx.x & 31;
    int wid  = threadIdx.x >> 5;
    int ca   = lane;            // channel A
    int cb   = lane + 32;       // channel B

    unsigned long long w2a[32], w2b[32];
#pragma unroll
    for (int i = 0; i < 32; i++) {
        w2a[i] = pack2(W2[(2 * i) * 64 + ca], W2[(2 * i + 1) * 64 + ca]);
        w2b[i] = pack2(W2[(2 * i) * 64 + cb], W2[(2 * i + 1) * 64 + cb]);
    }
    float w10a = W1[ca], w11a = W1[64 + ca], w12a = W1[128 + ca];
    float w10b = W1[cb], w11b = W1[64 + cb], w12b = W1[128 + cb];
    float b1a = b1[ca], b1b = b1[cb];
    float b2a = b2[ca], b2b = b2[cb];

    float* H = Hs[wid];
    float* G = Gs[wid];
    int gw = blockIdx.x * 4 + wid;

#pragma unroll 1
    for (int q = gw; q < QTOT; q += 4 * MLP_BLOCKS) {   // 4 iters/warp
        int b = q >> 13;
        int j16 = (lane < KNN) ? g_idx[(size_t)q * KNN + lane] : 0;
        float px = 0.0f, py = 0.0f, pz = 0.0f;
        if (lane < KNN) {
            const float* p = xyz1 + ((size_t)b * N + j16) * 3;
            px = p[0]; py = p[1]; pz = p[2];
        }
        const float* x2 = xyz2 + (size_t)q * 3;
        float qx = x2[0], qy = x2[1], qz = x2[2];
        const float* fb = g_f + (size_t)b * N * 64;

        // phase 1a: h channels (ca, cb) per k
#pragma unroll 8
        for (int k = 0; k < KNN; k++) {
            float gx = __shfl_sync(0xffffffffu, px, k) - qx;
            float gy = __shfl_sync(0xffffffffu, py, k) - qy;
            float gz = __shfl_sync(0xffffffffu, pz, k) - qz;
            float ha = fmaf(gz, w12a, fmaf(gy, w11a, fmaf(gx, w10a, b1a)));
            float hb = fmaf(gz, w12b, fmaf(gy, w11b, fmaf(gx, w10b, b1b)));
            H[k * 64 + ca] = fmaxf(ha, 0.0f);
            H[k * 64 + cb] = fmaxf(hb, 0.0f);
        }
        // phase 1b: gathered-feature staging (batched LDG)
#pragma unroll 8
        for (int k = 0; k < KNN; k++) {
            int j = __shfl_sync(0xffffffffu, j16, k);
            G[k * 64 + ca] = fb[(size_t)j * 64 + ca];
            G[k * 64 + cb] = fb[(size_t)j * 64 + cb];
        }
        __syncwarp();

        // phase 2: pw = b2 + h . W2col (packed f32x2); acc += pw * gf
        float acca = 0.0f, accb = 0.0f;
#pragma unroll 1
        for (int k = 0; k < KNN; k++) {
            float gfa = G[k * 64 + ca];
            float gfb = G[k * 64 + cb];
            const ulonglong2* h2 = (const ulonglong2*)(H + k * 64);
            unsigned long long pa0 = 0ull, pa1 = 0ull, pb0 = 0ull, pb1 = 0ull;
#pragma unroll
            for (int i = 0; i < 16; i++) {
                ulonglong2 hv = h2[i];
                pa0 = fma2(hv.x, w2a[2 * i],     pa0);
                pa1 = fma2(hv.y, w2a[2 * i + 1], pa1);
                pb0 = fma2(hv.x, w2b[2 * i],     pb0);
                pb1 = fma2(hv.y, w2b[2 * i + 1], pb1);
            }
            float a0, a1, a2, a3, c0, c1, c2, c3;
            unpack2(pa0, a0, a1); unpack2(pa1, a2, a3);
            unpack2(pb0, c0, c1); unpack2(pb1, c2, c3);
            float pwa = b2a + ((a0 + a1) + (a2 + a3));
            float pwb = b2b + ((c0 + c1) + (c2 + c3));
            acca = fmaf(pwa, gfa, acca);
            accb = fmaf(pwb, gfb, accb);
        }
        out[(size_t)q * 64 + ca] = acca * 0.25f;   // 1/sqrt(16)
        out[(size_t)q * 64 + cb] = accb * 0.25f;
        __syncwarp();   // H/G reads done before next query overwrites
    }
}

// ---------------------------------------------------------------------------
// launch
// ---------------------------------------------------------------------------
extern "C" void kernel_launch(void* const* d_in, const int* in_sizes, int n_in,
                              void* d_out, int out_size)
{
    const float* feature1 = (const float*)d_in[0];
    const float* xyz1     = (const float*)d_in[1];
    const float* xyz2     = (const float*)d_in[2];
    const float* Wp       = (const float*)d_in[3];
    const float* bp       = (const float*)d_in[4];
    const float* W1       = (const float*)d_in[5];
    const float* b1       = (const float*)d_in[6];
    const float* W2       = (const float*)d_in[7];
    const float* b2       = (const float*)d_in[8];

    float* out_feat = (float*)d_out;                       // [B*M*64]
    float* out_w    = (float*)d_out + (size_t)B * M * 64;  // [B*M]

    proj_kernel<<<(B * N) / 16, 256>>>(feature1, Wp, bp);

    dim3 kg(M / 128, NCHUNK, B);
    knn_part_kernel<<<kg, 128>>>(xyz1, xyz2);
    knn_merge_kernel<<<(QTOT + 255) / 256, 256>>>(xyz1, xyz2, out_w);

    mlp_kernel<<<MLP_BLOCKS, 128>>>(xyz1, xyz2, W1, b1, W2, b2, out_feat);
}

// round 16
// speedup vs baseline: 1.5172x; 1.5172x over previous
#include <cuda_runtime.h>
#include <cuda_bf16.h>

#define B 2
#define N 8192
#define M 8192
#define D 64
#define KNN 16
#define QTOT (B * M)

#define NCHUNK 8
#define CHUNK (N / NCHUNK)     // 1024
#define NGRP (CHUNK / 4)       // 256 packed groups
#define SENT 3.4e38f
#define EPSF 5e-5f             // t-space filter margin

// Scratch (allocation-free: __device__ globals)
__device__ float g_f[B * N * D];                    // projected features, 4MB
__device__ int   g_idx[B * M * KNN];                // final knn indices
__device__ float g_pd[B * M * NCHUNK * KNN];        // partial top-16 dists
__device__ int   g_pi[B * M * NCHUNK * KNN];        // partial top-16 ids

__device__ __forceinline__ unsigned long long fma2(
    unsigned long long a, unsigned long long b, unsigned long long c) {
    unsigned long long r;
    asm("fma.rn.f32x2 %0, %1, %2, %3;" : "=l"(r) : "l"(a), "l"(b), "l"(c));
    return r;
}
__device__ __forceinline__ unsigned long long mul2(
    unsigned long long a, unsigned long long b) {
    unsigned long long r;
    asm("mul.rn.f32x2 %0, %1, %2;" : "=l"(r) : "l"(a), "l"(b));
    return r;
}
__device__ __forceinline__ unsigned long long add2(
    unsigned long long a, unsigned long long b) {
    unsigned long long r;
    asm("add.rn.f32x2 %0, %1, %2;" : "=l"(r) : "l"(a), "l"(b));
    return r;
}
__device__ __forceinline__ unsigned long long pack2(float lo, float hi) {
    unsigned long long r;
    asm("mov.b64 %0, {%1, %2};" : "=l"(r) : "f"(lo), "f"(hi));
    return r;
}
__device__ __forceinline__ void unpack2(unsigned long long v, float& lo, float& hi) {
    asm("mov.b64 {%0, %1}, %2;" : "=f"(lo), "=f"(hi) : "l"(v));
}

// Per-query radius^2 threshold covering ~TARGET points in expectation.
// Performance hint only: merge kernel verifies completeness and falls back.
__device__ __forceinline__ float query_thresh(float qx, float qy, float qz) {
    const float TARGET = 48.0f;
    const float KVOL = (float)N * 4.18879f;   // N * (4/3)pi
    float r = cbrtf(TARGET / KVOL);
#pragma unroll
    for (int it = 0; it < 3; it++) {
        float inv2r = 0.5f / r;
        float fx = (fminf(qx, r) + fminf(1.0f - qx, r)) * inv2r;
        float fy = (fminf(qy, r) + fminf(1.0f - qy, r)) * inv2r;
        float fz = (fminf(qz, r) + fminf(1.0f - qz, r)) * inv2r;
        float c = fmaxf(fx * fy * fz, 0.125f);
        r = cbrtf(TARGET / (KVOL * c));
    }
    return r * r;
}

// ---------------------------------------------------------------------------
// Kernel 1: f = feature1 @ Wp + bp (16 rows/block)
// ---------------------------------------------------------------------------
__global__ __launch_bounds__(256) void proj_kernel(
    const float* __restrict__ feat, const float* __restrict__ Wp,
    const float* __restrict__ bp)
{
    __shared__ float Ws[64 * 64];
    __shared__ float Fs[16][64];
    for (int i = threadIdx.x; i < 64 * 64; i += 256) Ws[i] = Wp[i];
    int r0 = blockIdx.x * 16;
    for (int i = threadIdx.x; i < 16 * 64; i += 256)
        Fs[i >> 6][i & 63] = feat[(r0 + (i >> 6)) * 64 + (i & 63)];
    __syncthreads();
    int rr = threadIdx.x >> 6;
    int c  = threadIdx.x & 63;
    float a0 = bp[c], a1 = a0, a2 = a0, a3 = a0;
#pragma unroll
    for (int d = 0; d < 64; d++) {
        float w = Ws[d * 64 + c];
        a0 = fmaf(Fs[rr     ][d], w, a0);
        a1 = fmaf(Fs[rr +  4][d], w, a1);
        a2 = fmaf(Fs[rr +  8][d], w, a2);
        a3 = fmaf(Fs[rr + 12][d], w, a3);
    }
    g_f[(r0 + rr     ) * 64 + c] = a0;
    g_f[(r0 + rr +  4) * 64 + c] = a1;
    g_f[(r0 + rr +  8) * 64 + c] = a2;
    g_f[(r0 + rr + 12) * 64 + c] = a3;
}

// ---------------------------------------------------------------------------
// Kernel 2a: packed filtered scan with BITMASK compaction.
// The pass test is round-15's validated packed compare (sign of t - rhs,
// superset of margined {d < T}); instead of per-candidate appends, the 4
// sign bits per group fold into a 32-bit mask word (one STS per 8 groups,
// transposed layout -> conflict-free). Overflow is impossible (mask covers
// all 1024 candidates), so the only exactness guard needed is the merge's
// sentinel (<16 passers -> full scan). Replay walks set bits in ascending
// candidate order and recomputes d with the textually-original formula ->
// selection semantics identical. grid = (M/128, NCHUNK, B), block = 128
// ---------------------------------------------------------------------------
__global__ __launch_bounds__(128) void knn_part_kernel(
    const float* __restrict__ xyz1, const float* __restrict__ xyz2)
{
    __shared__ ulonglong2 PX[NGRP], PY[NGRP], PZ[NGRP], PW[NGRP]; // 16KB
    __shared__ unsigned   msk[32][128];                           // 16KB
    int b     = blockIdx.z;
    int chunk = blockIdx.y;
    int m     = blockIdx.x * 128 + threadIdx.x;
    const float* x2 = xyz2 + ((size_t)b * M + m) * 3;
    float qx = x2[0], qy = x2[1], qz = x2[2];
    float qs = qx * qx + qy * qy + qz * qz;
    float T  = query_thresh(qx, qy, qz);
    float u  = 0.5f * (qs - T) - EPSF;      // folded margin

    int nbeg = chunk * CHUNK;
    const float* base = xyz1 + ((size_t)b * N + nbeg) * 3;
    {
        int c0 = threadIdx.x * 8;            // 8 consecutive candidates/thread
        float xx[8], yy[8], zz[8];
#pragma unroll
        for (int i = 0; i < 8; i++) {
            xx[i] = base[(c0 + i) * 3 + 0];
            yy[i] = base[(c0 + i) * 3 + 1];
            zz[i] = base[(c0 + i) * 3 + 2];
        }
#pragma unroll
        for (int g = 0; g < 2; g++) {
            int o = g * 4;
            int gi = threadIdx.x * 2 + g;
            PX[gi] = make_ulonglong2(pack2(xx[o], xx[o + 1]), pack2(xx[o + 2], xx[o + 3]));
            PY[gi] = make_ulonglong2(pack2(yy[o], yy[o + 1]), pack2(yy[o + 2], yy[o + 3]));
            PZ[gi] = make_ulonglong2(pack2(zz[o], zz[o + 1]), pack2(zz[o + 2], zz[o + 3]));
            float w0 = xx[o    ] * xx[o    ] + yy[o    ] * yy[o    ] + zz[o    ] * zz[o    ];
            float w1 = xx[o + 1] * xx[o + 1] + yy[o + 1] * yy[o + 1] + zz[o + 1] * zz[o + 1];
            float w2 = xx[o + 2] * xx[o + 2] + yy[o + 2] * yy[o + 2] + zz[o + 2] * zz[o + 2];
            float w3 = xx[o + 3] * xx[o + 3] + yy[o + 3] * yy[o + 3] + zz[o + 3] * zz[o + 3];
            PW[gi] = make_ulonglong2(pack2(w0, w1), pack2(w2, w3));
        }
    }
    __syncthreads();

    unsigned long long qx2 = pack2(qx, qx), qy2 = pack2(qy, qy), qz2 = pack2(qz, qz);
    unsigned long long mh2 = pack2(-0.5f, -0.5f), mu2 = pack2(-u, -u);
    unsigned macc = 0;
#pragma unroll 8
    for (int g = 0; g < NGRP; g++) {
        ulonglong2 xv = PX[g], yv = PY[g], zv = PZ[g], wv = PW[g];
        // same fma sequence as original: t = qx*x; t=fma(qy,y,t); t=fma(qz,z,t)
        unsigned long long t0 = fma2(zv.x, qz2, fma2(yv.x, qy2, mul2(xv.x, qx2)));
        unsigned long long t1 = fma2(zv.y, qz2, fma2(yv.y, qy2, mul2(xv.y, qx2)));
        unsigned long long d0 = add2(t0, fma2(wv.x, mh2, mu2));   // t - (0.5w + u)
        unsigned long long d1 = add2(t1, fma2(wv.y, mh2, mu2));
        unsigned u0 = (unsigned)d0, u1 = (unsigned)(d0 >> 32);
        unsigned u2 = (unsigned)d1, u3 = (unsigned)(d1 >> 32);
        // pass = sign bit clear (f >= +0), identical to round-15 condition
        unsigned m4 = ((~u0) >> 31)
                    | (((~u1) >> 30) & 2u)
                    | (((~u2) >> 29) & 4u)
                    | (((~u3) >> 28) & 8u);
        macc |= m4 << (4 * (g & 7));
        if ((g & 7) == 7) { msk[g >> 3][threadIdx.x] = macc; macc = 0; }
    }

    // replay (ascending-n order): original formula, strict-< sorted insert
    const float* fx = (const float*)PX;   // linear float views of pair-SoA
    const float* fy = (const float*)PY;
    const float* fz = (const float*)PZ;
    const float* fw = (const float*)PW;
    float bd[KNN]; int bi[KNN];
#pragma unroll
    for (int j = 0; j < KNN; j++) { bd[j] = SENT; bi[j] = 0; }
#pragma unroll 1
    for (int w = 0; w < 32; w++) {
        unsigned mask = msk[w][threadIdx.x];
        while (mask) {
            int bit = __ffs(mask) - 1;
            mask &= mask - 1;
            int jj = w * 32 + bit;
            float x = fx[jj], y = fy[jj], z = fz[jj], pw = fw[jj];
            float t = qx * x;
            t = fmaf(qy, y, t);
            t = fmaf(qz, z, t);
            float d = (qs + pw) - 2.0f * t;   // bitwise-same as original kernel
            if (d < bd[KNN - 1]) {
                bd[KNN - 1] = d; bi[KNN - 1] = nbeg + jj;
#pragma unroll
                for (int j = KNN - 1; j > 0; --j) {
                    if (bd[j] < bd[j - 1]) {
                        float td = bd[j]; bd[j] = bd[j - 1]; bd[j - 1] = td;
                        int   ti = bi[j]; bi[j] = bi[j - 1]; bi[j - 1] = ti;
                    }
                }
            }
        }
    }

    size_t q = (size_t)b * M + m;
    float* pd = g_pd + (q * NCHUNK + chunk) * KNN;
    int*   pi = g_pi + (q * NCHUNK + chunk) * KNN;
#pragma unroll
    for (int j = 0; j < KNN; j++) { pd[j] = bd[j]; pi[j] = bi[j]; }
}

// ---------------------------------------------------------------------------
// Kernel 2b: exact 8-way merge; fallback to full scan on sentinel (<16
// candidates passed the filter) — sole, airtight exactness guard.
// ---------------------------------------------------------------------------
__global__ __launch_bounds__(256) void knn_merge_kernel(
    const float* __restrict__ xyz1, const float* __restrict__ xyz2,
    float* __restrict__ outW)
{
    int q = blockIdx.x * 256 + threadIdx.x;
    if (q >= QTOT) return;
    const float* pd = g_pd + (size_t)q * NCHUNK * KNN;
    const int*   pi = g_pi + (size_t)q * NCHUNK * KNN;

    int   ptr[NCHUNK];
    float head[NCHUNK];
#pragma unroll
    for (int c = 0; c < NCHUNK; c++) { ptr[c] = 0; head[c] = pd[c * KNN]; }

    int   outi[KNN];
    float first = SENT, last = SENT;
#pragma unroll
    for (int j = 0; j < KNN; j++) {
        int best = 0; float bv = head[0];
#pragma unroll
        for (int c = 1; c < NCHUNK; c++)
            if (head[c] < bv) { bv = head[c]; best = c; }   // earliest chunk wins ties
        outi[j] = pi[best * KNN + ptr[best]];
        if (j == 0) first = bv;
        last = bv;
        ptr[best]++;
        head[best] = (ptr[best] < KNN) ? pd[best * KNN + ptr[best]] : SENT;
    }

    if (last >= SENT) {
        // fallback: full unfiltered scan (exactness guarantee; ~never taken)
        int b = q >> 13;
        const float* x2 = xyz2 + (size_t)q * 3;
        float qx = x2[0], qy = x2[1], qz = x2[2];
        float qs = qx * qx + qy * qy + qz * qz;
        float bd[KNN];
#pragma unroll
        for (int j = 0; j < KNN; j++) { bd[j] = SENT; outi[j] = 0; }
        const float* base = xyz1 + (size_t)b * N * 3;
        for (int n = 0; n < N; n++) {
            float x = base[n * 3], y = base[n * 3 + 1], z = base[n * 3 + 2];
            float ps = x * x + y * y + z * z;
            float t = qx * x;
            t = fmaf(qy, y, t);
            t = fmaf(qz, z, t);
            float d = (qs + ps) - 2.0f * t;
            if (d < bd[KNN - 1]) {
                bd[KNN - 1] = d; outi[KNN - 1] = n;
#pragma unroll
                for (int j = KNN - 1; j > 0; --j) {
                    if (bd[j] < bd[j - 1]) {
                        float td = bd[j]; bd[j] = bd[j - 1]; bd[j - 1] = td;
                        int   ti = outi[j]; outi[j] = outi[j - 1]; outi[j - 1] = ti;
                    }
                }
            }
        }
        first = bd[0];
    }

#pragma unroll
    for (int j = 0; j < KNN; j++) g_idx[(size_t)q * KNN + j] = outi[j];
    outW[q] = (first > 0.03f) ? 10.0f : 1.0f;
}

// ---------------------------------------------------------------------------
// Kernel 3: gather + MLP + reduction — VERBATIM round-14 version (77us known:
// 168 regs / 3 blocks; the (128,4) spill variant thrashed L2 and regressed).
// ---------------------------------------------------------------------------
#define MLP_BLOCKS 1024         // 4096 warps -> exactly 4 queries each
__global__ __launch_bounds__(128, 3) void mlp_kernel(
    const float* __restrict__ xyz1, const float* __restrict__ xyz2,
    const float* __restrict__ W1, const float* __restrict__ b1,
    const float* __restrict__ W2, const float* __restrict__ b2,
    float* __restrict__ out)
{
    __shared__ float Hs[4][KNN * 64];   // 16KB
    __shared__ float Gs[4][KNN * 64];   // 16KB
    int lane = threadIdx.x & 31;
    int wid  = threadIdx.x >> 5;
    int ca   = lane;            // channel A
    int cb   = lane + 32;       // channel B

    unsigned long long w2a[32], w2b[32];
#pragma unroll
    for (int i = 0; i < 32; i++) {
        w2a[i] = pack2(W2[(2 * i) * 64 + ca], W2[(2 * i + 1) * 64 + ca]);
        w2b[i] = pack2(W2[(2 * i) * 64 + cb], W2[(2 * i + 1) * 64 + cb]);
    }
    float w10a = W1[ca], w11a = W1[64 + ca], w12a = W1[128 + ca];
    float w10b = W1[cb], w11b = W1[64 + cb], w12b = W1[128 + cb];
    float b1a = b1[ca], b1b = b1[cb];
    float b2a = b2[ca], b2b = b2[cb];

    float* H = Hs[wid];
    float* G = Gs[wid];
    int gw = blockIdx.x * 4 + wid;

#pragma unroll 1
    for (int q = gw; q < QTOT; q += 4 * MLP_BLOCKS) {   // 4 iters/warp
        int b = q >> 13;
        int j16 = (lane < KNN) ? g_idx[(size_t)q * KNN + lane] : 0;
        float px = 0.0f, py = 0.0f, pz = 0.0f;
        if (lane < KNN) {
            const float* p = xyz1 + ((size_t)b * N + j16) * 3;
            px = p[0]; py = p[1]; pz = p[2];
        }
        const float* x2 = xyz2 + (size_t)q * 3;
        float qx = x2[0], qy = x2[1], qz = x2[2];
        const float* fb = g_f + (size_t)b * N * 64;

        // phase 1a: h channels (ca, cb) per k
#pragma unroll 8
        for (int k = 0; k < KNN; k++) {
            float gx = __shfl_sync(0xffffffffu, px, k) - qx;
            float gy = __shfl_sync(0xffffffffu, py, k) - qy;
            float gz = __shfl_sync(0xffffffffu, pz, k) - qz;
            float ha = fmaf(gz, w12a, fmaf(gy, w11a, fmaf(gx, w10a, b1a)));
            float hb = fmaf(gz, w12b, fmaf(gy, w11b, fmaf(gx, w10b, b1b)));
            H[k * 64 + ca] = fmaxf(ha, 0.0f);
            H[k * 64 + cb] = fmaxf(hb, 0.0f);
        }
        // phase 1b: gathered-feature staging (batched LDG)
#pragma unroll 8
        for (int k = 0; k < KNN; k++) {
            int j = __shfl_sync(0xffffffffu, j16, k);
            G[k * 64 + ca] = fb[(size_t)j * 64 + ca];
            G[k * 64 + cb] = fb[(size_t)j * 64 + cb];
        }
        __syncwarp();

        // phase 2: pw = b2 + h . W2col (packed f32x2); acc += pw * gf
        float acca = 0.0f, accb = 0.0f;
#pragma unroll 1
        for (int k = 0; k < KNN; k++) {
            float gfa = G[k * 64 + ca];
            float gfb = G[k * 64 + cb];
            const ulonglong2* h2 = (const ulonglong2*)(H + k * 64);
            unsigned long long pa0 = 0ull, pa1 = 0ull, pb0 = 0ull, pb1 = 0ull;
#pragma unroll
            for (int i = 0; i < 16; i++) {
                ulonglong2 hv = h2[i];
                pa0 = fma2(hv.x, w2a[2 * i],     pa0);
                pa1 = fma2(hv.y, w2a[2 * i + 1], pa1);
                pb0 = fma2(hv.x, w2b[2 * i],     pb0);
                pb1 = fma2(hv.y, w2b[2 * i + 1], pb1);
            }
            float a0, a1, a2, a3, c0, c1, c2, c3;
            unpack2(pa0, a0, a1); unpack2(pa1, a2, a3);
            unpack2(pb0, c0, c1); unpack2(pb1, c2, c3);
            float pwa = b2a + ((a0 + a1) + (a2 + a3));
            float pwb = b2b + ((c0 + c1) + (c2 + c3));
            acca = fmaf(pwa, gfa, acca);
            accb = fmaf(pwb, gfb, accb);
        }
        out[(size_t)q * 64 + ca] = acca * 0.25f;   // 1/sqrt(16)
        out[(size_t)q * 64 + cb] = accb * 0.25f;
        __syncwarp();   // H/G reads done before next query overwrites
    }
}

// ---------------------------------------------------------------------------
// launch
// ---------------------------------------------------------------------------
extern "C" void kernel_launch(void* const* d_in, const int* in_sizes, int n_in,
                              void* d_out, int out_size)
{
    const float* feature1 = (const float*)d_in[0];
    const float* xyz1     = (const float*)d_in[1];
    const float* xyz2     = (const float*)d_in[2];
    const float* Wp       = (const float*)d_in[3];
    const float* bp       = (const float*)d_in[4];
    const float* W1       = (const float*)d_in[5];
    const float* b1       = (const float*)d_in[6];
    const float* W2       = (const float*)d_in[7];
    const float* b2       = (const float*)d_in[8];

    float* out_feat = (float*)d_out;                       // [B*M*64]
    float* out_w    = (float*)d_out + (size_t)B * M * 64;  // [B*M]

    proj_kernel<<<(B * N) / 16, 256>>>(feature1, Wp, bp);

    dim3 kg(M / 128, NCHUNK, B);
    knn_part_kernel<<<kg, 128>>>(xyz1, xyz2);
    knn_merge_kernel<<<(QTOT + 255) / 256, 256>>>(xyz1, xyz2, out_w);

    mlp_kernel<<<MLP_BLOCKS, 128>>>(xyz1, xyz2, W1, b1, W2, b2, out_feat);
}